// round 15
// baseline (speedup 1.0000x reference)
#include <cuda_runtime.h>
#include <cuda_bf16.h>
#include <mma.h>
#include <cstdint>

using namespace nvcuda;

// ---------------------------------------------------------------------------
// Problem constants
// ---------------------------------------------------------------------------
#define BATCH 1024
#define NN    112            // graph size
#define ADJS  116            // GNN adj row stride: %4==0 (legal wmma ldm),
                             // %32==20 -> 8 fragment rows hit 8 distinct banks
#define EPIS  113            // epi transpose stride: odd -> all 32 banks
#define GK    7168           // N * 64  (flattened GNN output per batch)
#define GN    12544          // N * N   (linear output per batch)

// ---------------------------------------------------------------------------
// Scratch (device globals: allocation-free rule)
// ---------------------------------------------------------------------------
__device__ __align__(16) __nv_bfloat16 g_H [(size_t)BATCH * GK];   // 14.7 MB
__device__ __align__(16) __nv_bfloat16 g_Wb[(size_t)GN * GK];      // 180 MB

// ---------------------------------------------------------------------------
// cp.async helpers
// ---------------------------------------------------------------------------
__device__ __forceinline__ uint32_t smem_u32(const void* p) {
    uint32_t a;
    asm("{ .reg .u64 t; cvta.to.shared.u64 t, %1; cvt.u32.u64 %0, t; }"
        : "=r"(a) : "l"(p));
    return a;
}
__device__ __forceinline__ void cp_async16(uint32_t sdst, const void* gsrc) {
    asm volatile("cp.async.cg.shared.global [%0], [%1], 16;"
                 :: "r"(sdst), "l"(__cvta_generic_to_global(gsrc)) : "memory");
}
#define CP_COMMIT() asm volatile("cp.async.commit_group;" ::: "memory")
#define CP_WAIT4()  asm volatile("cp.async.wait_group 4;" ::: "memory")
#define CP_WAIT0()  asm volatile("cp.async.wait_group 0;" ::: "memory")

// ===========================================================================
// GNN kernel (fused with W conversion): blocks [0,1024) do the GNN,
// blocks [1024, 22976) convert Wlin fp32 -> g_Wb bf16 (overlapped, DRAM-bound).
// ===========================================================================
__device__ __forceinline__ float mishf(float s) {
    float sp = (s > 20.f) ? s : log1pf(expf(s));
    return s * tanhf(sp);
}

// t[112 x Cs] = adj[112 x 112] @ h[112 x Cs] on TF32 tensor cores.
// ntc = number of 16-wide column tiles. All strides %4==0 (legal ldm) and
// not %32==0 (bank-conflict-free fragment rows).
__device__ void adj_h_wmma(int Cs, int ntc, const float* s_adj,
                           const float* h, float* t, int wid)
{
    for (int tile = wid; tile < 7 * ntc; tile += 16) {
        int tr = tile / ntc;
        int tc = tile - tr * ntc;
        wmma::fragment<wmma::accumulator, 16, 16, 8, float> acc;
        wmma::fill_fragment(acc, 0.f);
        #pragma unroll
        for (int k0 = 0; k0 < NN; k0 += 8) {
            wmma::fragment<wmma::matrix_a, 16, 16, 8, wmma::precision::tf32, wmma::row_major> fa;
            wmma::fragment<wmma::matrix_b, 16, 16, 8, wmma::precision::tf32, wmma::row_major> fb;
            wmma::load_matrix_sync(fa, s_adj + tr * 16 * ADJS + k0, ADJS);
            wmma::load_matrix_sync(fb, h + k0 * Cs + tc * 16, Cs);
            #pragma unroll
            for (int i = 0; i < fa.num_elements; i++) fa.x[i] = wmma::__float_to_tf32(fa.x[i]);
            #pragma unroll
            for (int i = 0; i < fb.num_elements; i++) fb.x[i] = wmma::__float_to_tf32(fb.x[i]);
            wmma::mma_sync(acc, fa, fb, acc);
        }
        wmma::store_matrix_sync(t + tr * 16 * Cs + tc * 16, acc, Cs, wmma::mem_row_major);
    }
}

// CsIn: input/t stride; CsOut: output stride (>= Cout, x4B is 16B-aligned).
__device__ void cheb_layer(int Cin, int CsIn, int ntc, int Cout, int CsOut,
                           bool use_wmma,
                           const float* __restrict__ W,
                           const float* __restrict__ bias,
                           const float* h, float* t, float* o,
                           const float* s_adj, int tid)
{
    if (use_wmma) {
        adj_h_wmma(CsIn, ntc, s_adj, h, t, tid >> 5);
    } else {
        // scalar path (L1, CsIn=4): 2-row float4 blocking
        const int quads = CsIn >> 2;
        const float4* h4 = reinterpret_cast<const float4*>(h);
        float4* t4 = reinterpret_cast<float4*>(t);
        for (int idx = tid; idx < 56 * quads; idx += 512) {
            int i  = idx / quads;
            int cq = idx - i * quads;
            const float* a0 = s_adj + i * ADJS;
            const float* a1 = s_adj + (i + 56) * ADJS;
            float4 s0 = make_float4(0.f, 0.f, 0.f, 0.f);
            float4 s1 = make_float4(0.f, 0.f, 0.f, 0.f);
            #pragma unroll 4
            for (int j = 0; j < NN; j++) {
                float av0 = a0[j];
                float av1 = a1[j];
                float4 hv = h4[j * quads + cq];
                s0.x += av0 * hv.x; s0.y += av0 * hv.y;
                s0.z += av0 * hv.z; s0.w += av0 * hv.w;
                s1.x += av1 * hv.x; s1.y += av1 * hv.y;
                s1.z += av1 * hv.z; s1.w += av1 * hv.w;
            }
            t4[i * quads + cq]        = s0;
            t4[(i + 56) * quads + cq] = s1;
        }
    }
    __syncthreads();

    // ---- o = mish(h@W0 + t@W1 + b): 2 rows (i, i+56) x 4 cols per thread ----
    const float* W0 = W;
    const float* W1 = W + Cin * Cout;
    const int nOut4 = Cout >> 2;
    for (int idx = tid; idx < 56 * nOut4; idx += 512) {
        int i  = idx / nOut4;
        int og = idx - i * nOut4;
        int oc = og << 2;
        float4 bb = *reinterpret_cast<const float4*>(bias + oc);
        float4 s0 = bb, s1 = bb;
        const float* h0 = h + i * CsIn;
        const float* h1 = h + (i + 56) * CsIn;
        const float* t0 = t + i * CsIn;
        const float* t1 = t + (i + 56) * CsIn;
        for (int c = 0; c < Cin; c++) {
            float ha = h0[c], hb = h1[c];
            float ta = t0[c], tb = t1[c];
            float4 w0 = __ldg(reinterpret_cast<const float4*>(W0 + c * Cout + oc));
            float4 w1 = __ldg(reinterpret_cast<const float4*>(W1 + c * Cout + oc));
            s0.x += ha * w0.x + ta * w1.x;  s0.y += ha * w0.y + ta * w1.y;
            s0.z += ha * w0.z + ta * w1.z;  s0.w += ha * w0.w + ta * w1.w;
            s1.x += hb * w0.x + tb * w1.x;  s1.y += hb * w0.y + tb * w1.y;
            s1.z += hb * w0.z + tb * w1.z;  s1.w += hb * w0.w + tb * w1.w;
        }
        float4 r0, r1;
        r0.x = mishf(s0.x); r0.y = mishf(s0.y); r0.z = mishf(s0.z); r0.w = mishf(s0.w);
        r1.x = mishf(s1.x); r1.y = mishf(s1.y); r1.z = mishf(s1.z); r1.w = mishf(s1.w);
        *reinterpret_cast<float4*>(o + i * CsOut + oc)        = r0;
        *reinterpret_cast<float4*>(o + (i + 56) * CsOut + oc) = r1;
    }
    __syncthreads();
}

// smem layout (floats): adj[116*112=12992] | b0[14784] | b1[14784] | b2[14784]
// = 229376 bytes dynamic. Buffer strides: 68 (w=64), 84 (w=65->80), 132 (w=128)
// — all %4==0 (legal ldm) and %32 in {4,20} (conflict-free).
__global__ void __launch_bounds__(512)
gnn_kernel(const float* __restrict__ x, const float* __restrict__ a,
           const int* __restrict__ label,
           const float* __restrict__ We1, const float* __restrict__ be1,
           const float* __restrict__ We2, const float* __restrict__ be2,
           const float* __restrict__ Wg1, const float* __restrict__ bg1,
           const float* __restrict__ Wg2, const float* __restrict__ bg2,
           const float* __restrict__ emb,
           const float* __restrict__ Wlin)
{
    int b   = blockIdx.x;
    int tid = threadIdx.x;

    // ---- wconv blocks: fp32 -> bf16, 8 elems/thread, no smem/sync ----
    if (b >= BATCH) {
        size_t base = ((size_t)(b - BATCH) * 512 + tid) * 8;
        float4 f0 = *reinterpret_cast<const float4*>(Wlin + base);
        float4 f1 = *reinterpret_cast<const float4*>(Wlin + base + 4);
        __nv_bfloat162 p[4];
        p[0] = __floats2bfloat162_rn(f0.x, f0.y);
        p[1] = __floats2bfloat162_rn(f0.z, f0.w);
        p[2] = __floats2bfloat162_rn(f1.x, f1.y);
        p[3] = __floats2bfloat162_rn(f1.z, f1.w);
        *reinterpret_cast<uint4*>(g_Wb + base) = *reinterpret_cast<uint4*>(p);
        return;
    }

    extern __shared__ float sm[];
    float* s_adj = sm;                     // 12992
    float* s_b0  = sm + 12992;             // 14784
    float* s_b1  = s_b0 + 14784;           // 14784
    float* s_b2  = s_b1 + 14784;           // 14784
    __shared__ float s_dinv[NN];
    __shared__ float s_lab[NN];

    const float* ab = a + (size_t)b * (NN * NN);
    for (int i = tid; i < NN * NN; i += 512) {
        int r = i / NN, c = i - r * NN;
        s_adj[r * ADJS + c] = ab[i];
    }
    int lb = label[b];
    for (int n = tid; n < NN; n += 512) s_lab[n] = emb[lb * NN + n];
    __syncthreads();

    for (int i = tid; i < NN; i += 512) {
        float s = 0.f;
        const float* row = s_adj + i * ADJS;
        for (int j = 0; j < NN; j++) s += row[j];
        s_dinv[i] = (s > 0.f) ? rsqrtf(fmaxf(s, 1e-12f)) : 0.f;
    }
    __syncthreads();
    for (int i = tid; i < NN * NN; i += 512) {
        int r = i / NN, c = i - r * NN;
        s_adj[r * ADJS + c] *= s_dinv[r] * s_dinv[c];
    }
    // h0 = [x | lab], Cin=4, stride 4
    for (int i = tid; i < NN * 4; i += 512) {
        int n = i >> 2, c = i & 3;
        s_b0[i] = (c < 3) ? x[((size_t)b * NN + n) * 3 + c] : s_lab[n];
    }
    __syncthreads();

    float* h = s_b0; float* t = s_b1; float* o = s_b2; float* tmp;

    cheb_layer(4, 4, 0, 64, 68, false, We1, be1, h, t, o, s_adj, tid);
    tmp = h; h = o; o = tmp;
    cheb_layer(64, 68, 4, 64, 68, true, We2, be2, h, t, o, s_adj, tid);
    tmp = h; h = o; o = tmp;

    // concat lab -> 65 channels, stride 84 (cols 65..83 zero for wmma overrun)
    for (int idx = tid; idx < NN * 84; idx += 512) {
        int n = idx / 84, c = idx - n * 84;
        float v;
        if (c < 64)       v = h[n * 68 + c];
        else if (c == 64) v = s_lab[n];
        else              v = 0.f;
        o[idx] = v;
    }
    __syncthreads();
    tmp = h; h = o; o = tmp;

    cheb_layer(65, 84, 5, 128, 132, true, Wg1, bg1, h, t, o, s_adj, tid);
    tmp = h; h = o; o = tmp;
    cheb_layer(128, 132, 8, 64, 68, true, Wg2, bg2, h, t, o, s_adj, tid);

    // export: o stride 68, logical width 64
    __nv_bfloat16* Hb = g_H + (size_t)b * GK;
    for (int idx = tid; idx < GK; idx += 512) {
        int n = idx >> 6, c = idx & 63;
        Hb[idx] = __float2bfloat16(o[n * 68 + c]);
    }
}

// ===========================================================================
// GEMM: Y = tanh(H[1024,7168] @ Wb[12544,7168]^T + bias)    (both bf16)
// WMMA m16n16k16, CTA tile 128x256, warp tile 64x64 (8 warps, 2x4),
// BK=32, 6-stage cp.async pipeline, ONE __syncthreads per k-iteration.
// (byte-identical to the R13 pass)
// ===========================================================================
#define NKT      224         // 7168 / 32
#define NSTG     6
#define AST      10240       // A stage bytes: 128 rows * 80B (stride 40 bf16)
#define STG      30720       // A + B per stage
#define ROWB     80          // bytes per smem row (40 bf16)

__global__ void __launch_bounds__(256, 1)
gemm_kernel(const float* __restrict__ bias, float* __restrict__ Y)
{
    extern __shared__ char smem_raw[];
    const uint32_t sbase = smem_u32(smem_raw);
    __nv_bfloat16* sA = reinterpret_cast<__nv_bfloat16*>(smem_raw);

    const int tid  = threadIdx.x;
    const int wid  = tid >> 5;
    const int lane = tid & 31;
    const int wm   = wid >> 2;           // 2 warp rows (M, 64 each)
    const int wn   = wid & 3;            // 4 warp cols (N, 64 each)
    const int am   = blockIdx.x * 128;   // M tile (x fastest -> W L2 reuse)
    const int bn   = blockIdx.y * 256;   // N tile

    const __nv_bfloat16* A = g_H;
    const __nv_bfloat16* B = g_Wb;

    wmma::fragment<wmma::accumulator, 16, 16, 16, float> acc[4][4];
    #pragma unroll
    for (int i = 0; i < 4; i++)
        #pragma unroll
        for (int j = 0; j < 4; j++)
            wmma::fill_fragment(acc[i][j], 0.f);

    // stage loader: 1536 x 16B chunks (512 A + 1024 B), 6 per thread
    auto load_stage = [&](int it) {
        const uint32_t ss = sbase + (it % NSTG) * STG;
        const int k0 = it * 32;
        #pragma unroll
        for (int u = 0; u < 2; u++) {              // A: ids 0..511
            int id  = tid + u * 256;
            int row = id >> 2, q = id & 3;
            cp_async16(ss + row * ROWB + q * 16,
                       A + (size_t)(am + row) * GK + k0 + q * 8);
        }
        #pragma unroll
        for (int u = 0; u < 4; u++) {              // B: ids 0..1023
            int id  = tid + u * 256;
            int row = id >> 2, q = id & 3;
            cp_async16(ss + AST + row * ROWB + q * 16,
                       B + (size_t)(bn + row) * GK + k0 + q * 8);
        }
    };

    // prologue: stages 0..4 (5 groups in flight)
    load_stage(0); CP_COMMIT();
    load_stage(1); CP_COMMIT();
    load_stage(2); CP_COMMIT();
    load_stage(3); CP_COMMIT();
    load_stage(4); CP_COMMIT();

    for (int kt = 0; kt < NKT; kt++) {
        CP_WAIT4();                  // stage kt resident (<=4 groups pending)
        __syncthreads();             // all threads see stage kt; all done with
                                     // slot (kt-1)%6 which we overwrite below

        const int s = kt % NSTG;
        const __nv_bfloat16* As = sA + s * (STG / 2);
        const __nv_bfloat16* Bs = As + (AST / 2);
        #pragma unroll
        for (int kk = 0; kk < 32; kk += 16) {
            wmma::fragment<wmma::matrix_a, 16, 16, 16, __nv_bfloat16, wmma::row_major> fa[4];
            wmma::fragment<wmma::matrix_b, 16, 16, 16, __nv_bfloat16, wmma::col_major> fb[4];
            #pragma unroll
            for (int i = 0; i < 4; i++)
                wmma::load_matrix_sync(fa[i], As + (wm * 64 + i * 16) * 40 + kk, 40);
            #pragma unroll
            for (int j = 0; j < 4; j++)
                wmma::load_matrix_sync(fb[j], Bs + (wn * 64 + j * 16) * 40 + kk, 40);
            #pragma unroll
            for (int i = 0; i < 4; i++)
                #pragma unroll
                for (int j = 0; j < 4; j++)
                    wmma::mma_sync(acc[i][j], fa[i], fb[j], acc[i][j]);
        }

        // prefetch stage kt+5 into slot (kt+5)%6 == (kt-1)%6 (safe: consumed
        // before the barrier above)
        if (kt + 5 < NKT) load_stage(kt + 5);
        CP_COMMIT();                 // one group per iteration (may be empty)
    }
    CP_WAIT0();
    __syncthreads();

    // --- epilogue: bias + tanh, per-warp smem scratch (stride 20 floats) ---
    float* scr = reinterpret_cast<float*>(smem_raw) + wid * (16 * 20);
    #pragma unroll
    for (int fm = 0; fm < 4; fm++) {
        #pragma unroll
        for (int fn = 0; fn < 4; fn++) {
            wmma::store_matrix_sync(scr, acc[fm][fn], 20, wmma::mem_row_major);
            __syncwarp();
            int gm0 = am + wm * 64 + fm * 16;
            int gn0 = bn + wn * 64 + fn * 16;
            #pragma unroll
            for (int e = lane; e < 256; e += 32) {
                int r = e >> 4, c = e & 15;
                int gn = gn0 + c;
                float v = tanhf(scr[r * 20 + c] + __ldg(bias + gn));
                Y[(size_t)(gm0 + r) * GN + gn] = v;
            }
            __syncwarp();
        }
    }
}

// ===========================================================================
// Epilogue: in-place symmetrize + arctanh + diagonal (smem-tiled).
// Transpose buffer stride 113 (odd): the strided read walks all 32 banks.
// ===========================================================================
__global__ void __launch_bounds__(256)
epi_kernel(float* __restrict__ out)
{
    extern __shared__ float sY[];          // 112*113 floats
    int b   = blockIdx.x;
    int tid = threadIdx.x;
    float* Yb = out + (size_t)b * GN;

    for (int i = tid; i < GN; i += 256) {
        int r = i / NN, c = i - r * NN;
        sY[r * EPIS + c] = Yb[i];
    }
    __syncthreads();

    for (int i = tid; i < GN; i += 256) {
        int r = i / NN;
        int c = i - r * NN;
        float v;
        if (r == c) v = 1.0f;
        else        v = atanhf(0.4995f * (sY[r * EPIS + c] + sY[c * EPIS + r]));
        Yb[i] = v;
    }
}

// ===========================================================================
// Launch
// ===========================================================================
extern "C" void kernel_launch(void* const* d_in, const int* in_sizes, int n_in,
                              void* d_out, int out_size)
{
    const float* x     = (const float*)d_in[0];
    const float* a     = (const float*)d_in[1];
    const int*   label = (const int*)  d_in[2];
    const float* We1   = (const float*)d_in[3];
    const float* be1   = (const float*)d_in[4];
    const float* We2   = (const float*)d_in[5];
    const float* be2   = (const float*)d_in[6];
    const float* Wg1   = (const float*)d_in[7];
    const float* bg1   = (const float*)d_in[8];
    const float* Wg2   = (const float*)d_in[9];
    const float* bg2   = (const float*)d_in[10];
    const float* Wlin  = (const float*)d_in[11];
    const float* blin  = (const float*)d_in[12];
    const float* emb   = (const float*)d_in[13];
    float* out = (float*)d_out;

    const int gnn_smem  = (12992 + 3 * 14784) * 4;   // 229376 B
    const int gemm_smem = NSTG * STG;                // 184320 B
    const int epi_smem  = NN * EPIS * 4;             // 50624 B
    cudaFuncSetAttribute(gnn_kernel,  cudaFuncAttributeMaxDynamicSharedMemorySize, gnn_smem);
    cudaFuncSetAttribute(gemm_kernel, cudaFuncAttributeMaxDynamicSharedMemorySize, gemm_smem);
    cudaFuncSetAttribute(epi_kernel,  cudaFuncAttributeMaxDynamicSharedMemorySize, epi_smem);

    // fused: 1024 GNN blocks + 21952 wconv blocks (89,915,392 / (512*8))
    const int wconv_blocks = (int)(((size_t)GN * GK) / 4096);
    gnn_kernel<<<BATCH + wconv_blocks, 512, gnn_smem>>>(
        x, a, label, We1, be1, We2, be2, Wg1, bg1, Wg2, bg2, emb, Wlin);

    dim3 ggrid(BATCH / 128, GN / 256);   // (8, 49)
    gemm_kernel<<<ggrid, 256, gemm_smem>>>(blin, out);

    epi_kernel<<<BATCH, 256, epi_smem>>>(out);
}

// round 16
// speedup vs baseline: 1.0312x; 1.0312x over previous
#include <cuda_runtime.h>
#include <cuda_bf16.h>
#include <mma.h>
#include <cstdint>

using namespace nvcuda;

// ---------------------------------------------------------------------------
// Problem constants
// ---------------------------------------------------------------------------
#define BATCH 1024
#define NN    112            // graph size
#define ADJS  116            // GNN adj row stride: %4==0 (legal wmma ldm),
                             // %32==20 -> 8 fragment rows hit 8 distinct banks
#define EPIS  113            // epi transpose stride: odd -> all 32 banks
#define GK    7168           // N * 64  (flattened GNN output per batch)
#define GN    12544          // N * N   (linear output per batch)

// ---------------------------------------------------------------------------
// Scratch (device globals: allocation-free rule)
// ---------------------------------------------------------------------------
__device__ __align__(16) __nv_bfloat16 g_H [(size_t)BATCH * GK];   // 14.7 MB
__device__ __align__(16) __nv_bfloat16 g_Wb[(size_t)GN * GK];      // 180 MB

// ---------------------------------------------------------------------------
// cp.async helpers
// ---------------------------------------------------------------------------
__device__ __forceinline__ uint32_t smem_u32(const void* p) {
    uint32_t a;
    asm("{ .reg .u64 t; cvta.to.shared.u64 t, %1; cvt.u32.u64 %0, t; }"
        : "=r"(a) : "l"(p));
    return a;
}
__device__ __forceinline__ void cp_async16(uint32_t sdst, const void* gsrc) {
    asm volatile("cp.async.cg.shared.global [%0], [%1], 16;"
                 :: "r"(sdst), "l"(__cvta_generic_to_global(gsrc)) : "memory");
}
#define CP_COMMIT() asm volatile("cp.async.commit_group;" ::: "memory")
#define CP_WAIT4()  asm volatile("cp.async.wait_group 4;" ::: "memory")
#define CP_WAIT0()  asm volatile("cp.async.wait_group 0;" ::: "memory")

// ===========================================================================
// GNN kernel: one CTA / batch element, 512 threads, all state in smem.
// ===========================================================================
__device__ __forceinline__ float mishf(float s) {
    float sp = (s > 20.f) ? s : log1pf(expf(s));
    return s * tanhf(sp);
}

// t[112 x Cs] = adj[112 x 112] @ h[112 x Cs] on TF32 tensor cores.
// ntc = number of 16-wide column tiles. All strides %4==0 (legal ldm) and
// not %32==0 (bank-conflict-free fragment rows).
__device__ void adj_h_wmma(int Cs, int ntc, const float* s_adj,
                           const float* h, float* t, int wid)
{
    for (int tile = wid; tile < 7 * ntc; tile += 16) {
        int tr = tile / ntc;
        int tc = tile - tr * ntc;
        wmma::fragment<wmma::accumulator, 16, 16, 8, float> acc;
        wmma::fill_fragment(acc, 0.f);
        #pragma unroll
        for (int k0 = 0; k0 < NN; k0 += 8) {
            wmma::fragment<wmma::matrix_a, 16, 16, 8, wmma::precision::tf32, wmma::row_major> fa;
            wmma::fragment<wmma::matrix_b, 16, 16, 8, wmma::precision::tf32, wmma::row_major> fb;
            wmma::load_matrix_sync(fa, s_adj + tr * 16 * ADJS + k0, ADJS);
            wmma::load_matrix_sync(fb, h + k0 * Cs + tc * 16, Cs);
            #pragma unroll
            for (int i = 0; i < fa.num_elements; i++) fa.x[i] = wmma::__float_to_tf32(fa.x[i]);
            #pragma unroll
            for (int i = 0; i < fb.num_elements; i++) fb.x[i] = wmma::__float_to_tf32(fb.x[i]);
            wmma::mma_sync(acc, fa, fb, acc);
        }
        wmma::store_matrix_sync(t + tr * 16 * Cs + tc * 16, acc, Cs, wmma::mem_row_major);
    }
}

// CsIn: input/t stride; CsOut: output stride (>= Cout, x4B is 16B-aligned).
__device__ void cheb_layer(int Cin, int CsIn, int ntc, int Cout, int CsOut,
                           bool use_wmma,
                           const float* __restrict__ W,
                           const float* __restrict__ bias,
                           const float* h, float* t, float* o,
                           const float* s_adj, int tid)
{
    if (use_wmma) {
        adj_h_wmma(CsIn, ntc, s_adj, h, t, tid >> 5);
    } else {
        // scalar path (L1, CsIn=4): 2-row float4 blocking
        const int quads = CsIn >> 2;
        const float4* h4 = reinterpret_cast<const float4*>(h);
        float4* t4 = reinterpret_cast<float4*>(t);
        for (int idx = tid; idx < 56 * quads; idx += 512) {
            int i  = idx / quads;
            int cq = idx - i * quads;
            const float* a0 = s_adj + i * ADJS;
            const float* a1 = s_adj + (i + 56) * ADJS;
            float4 s0 = make_float4(0.f, 0.f, 0.f, 0.f);
            float4 s1 = make_float4(0.f, 0.f, 0.f, 0.f);
            #pragma unroll 4
            for (int j = 0; j < NN; j++) {
                float av0 = a0[j];
                float av1 = a1[j];
                float4 hv = h4[j * quads + cq];
                s0.x += av0 * hv.x; s0.y += av0 * hv.y;
                s0.z += av0 * hv.z; s0.w += av0 * hv.w;
                s1.x += av1 * hv.x; s1.y += av1 * hv.y;
                s1.z += av1 * hv.z; s1.w += av1 * hv.w;
            }
            t4[i * quads + cq]        = s0;
            t4[(i + 56) * quads + cq] = s1;
        }
    }
    __syncthreads();

    // ---- o = mish(h@W0 + t@W1 + b): 2 rows (i, i+56) x 4 cols per thread ----
    const float* W0 = W;
    const float* W1 = W + Cin * Cout;
    const int nOut4 = Cout >> 2;
    for (int idx = tid; idx < 56 * nOut4; idx += 512) {
        int i  = idx / nOut4;
        int og = idx - i * nOut4;
        int oc = og << 2;
        float4 bb = *reinterpret_cast<const float4*>(bias + oc);
        float4 s0 = bb, s1 = bb;
        const float* h0 = h + i * CsIn;
        const float* h1 = h + (i + 56) * CsIn;
        const float* t0 = t + i * CsIn;
        const float* t1 = t + (i + 56) * CsIn;
        for (int c = 0; c < Cin; c++) {
            float ha = h0[c], hb = h1[c];
            float ta = t0[c], tb = t1[c];
            float4 w0 = __ldg(reinterpret_cast<const float4*>(W0 + c * Cout + oc));
            float4 w1 = __ldg(reinterpret_cast<const float4*>(W1 + c * Cout + oc));
            s0.x += ha * w0.x + ta * w1.x;  s0.y += ha * w0.y + ta * w1.y;
            s0.z += ha * w0.z + ta * w1.z;  s0.w += ha * w0.w + ta * w1.w;
            s1.x += hb * w0.x + tb * w1.x;  s1.y += hb * w0.y + tb * w1.y;
            s1.z += hb * w0.z + tb * w1.z;  s1.w += hb * w0.w + tb * w1.w;
        }
        float4 r0, r1;
        r0.x = mishf(s0.x); r0.y = mishf(s0.y); r0.z = mishf(s0.z); r0.w = mishf(s0.w);
        r1.x = mishf(s1.x); r1.y = mishf(s1.y); r1.z = mishf(s1.z); r1.w = mishf(s1.w);
        *reinterpret_cast<float4*>(o + i * CsOut + oc)        = r0;
        *reinterpret_cast<float4*>(o + (i + 56) * CsOut + oc) = r1;
    }
    __syncthreads();
}

// smem layout (floats): adj[116*112=12992] | b0[14784] | b1[14784] | b2[14784]
// = 229376 bytes dynamic. Buffer strides: 68 (w=64), 84 (w=65->80), 132 (w=128)
// — all %4==0 (legal ldm) and %32 in {4,20} (conflict-free).
__global__ void __launch_bounds__(512)
gnn_kernel(const float* __restrict__ x, const float* __restrict__ a,
           const int* __restrict__ label,
           const float* __restrict__ We1, const float* __restrict__ be1,
           const float* __restrict__ We2, const float* __restrict__ be2,
           const float* __restrict__ Wg1, const float* __restrict__ bg1,
           const float* __restrict__ Wg2, const float* __restrict__ bg2,
           const float* __restrict__ emb)
{
    int b   = blockIdx.x;
    int tid = threadIdx.x;

    extern __shared__ float sm[];
    float* s_adj = sm;                     // 12992
    float* s_b0  = sm + 12992;             // 14784
    float* s_b1  = s_b0 + 14784;           // 14784
    float* s_b2  = s_b1 + 14784;           // 14784
    __shared__ float s_dinv[NN];
    __shared__ float s_lab[NN];

    const float* ab = a + (size_t)b * (NN * NN);
    for (int i = tid; i < NN * NN; i += 512) {
        int r = i / NN, c = i - r * NN;
        s_adj[r * ADJS + c] = ab[i];
    }
    int lb = label[b];
    for (int n = tid; n < NN; n += 512) s_lab[n] = emb[lb * NN + n];
    __syncthreads();

    for (int i = tid; i < NN; i += 512) {
        float s = 0.f;
        const float* row = s_adj + i * ADJS;
        for (int j = 0; j < NN; j++) s += row[j];
        s_dinv[i] = (s > 0.f) ? rsqrtf(fmaxf(s, 1e-12f)) : 0.f;
    }
    __syncthreads();
    for (int i = tid; i < NN * NN; i += 512) {
        int r = i / NN, c = i - r * NN;
        s_adj[r * ADJS + c] *= s_dinv[r] * s_dinv[c];
    }
    // h0 = [x | lab], Cin=4, stride 4
    for (int i = tid; i < NN * 4; i += 512) {
        int n = i >> 2, c = i & 3;
        s_b0[i] = (c < 3) ? x[((size_t)b * NN + n) * 3 + c] : s_lab[n];
    }
    __syncthreads();

    float* h = s_b0; float* t = s_b1; float* o = s_b2; float* tmp;

    cheb_layer(4, 4, 0, 64, 68, false, We1, be1, h, t, o, s_adj, tid);
    tmp = h; h = o; o = tmp;
    cheb_layer(64, 68, 4, 64, 68, true, We2, be2, h, t, o, s_adj, tid);
    tmp = h; h = o; o = tmp;

    // concat lab -> 65 channels, stride 84 (cols 65..83 zero for wmma overrun)
    for (int idx = tid; idx < NN * 84; idx += 512) {
        int n = idx / 84, c = idx - n * 84;
        float v;
        if (c < 64)       v = h[n * 68 + c];
        else if (c == 64) v = s_lab[n];
        else              v = 0.f;
        o[idx] = v;
    }
    __syncthreads();
    tmp = h; h = o; o = tmp;

    cheb_layer(65, 84, 5, 128, 132, true, Wg1, bg1, h, t, o, s_adj, tid);
    tmp = h; h = o; o = tmp;
    cheb_layer(128, 132, 8, 64, 68, true, Wg2, bg2, h, t, o, s_adj, tid);

    // export: o stride 68, logical width 64
    __nv_bfloat16* Hb = g_H + (size_t)b * GK;
    for (int idx = tid; idx < GK; idx += 512) {
        int n = idx >> 6, c = idx & 63;
        Hb[idx] = __float2bfloat16(o[n * 68 + c]);
    }
}

// ===========================================================================
// W fp32 -> bf16 conversion (standalone: zero smem -> full occupancy, DRAM-bound)
// ===========================================================================
__global__ void __launch_bounds__(256)
wconv_kernel(const float* __restrict__ W)
{
    size_t base = ((size_t)blockIdx.x * 256 + threadIdx.x) * 8;
    float4 f0 = *reinterpret_cast<const float4*>(W + base);
    float4 f1 = *reinterpret_cast<const float4*>(W + base + 4);
    __nv_bfloat162 p[4];
    p[0] = __floats2bfloat162_rn(f0.x, f0.y);
    p[1] = __floats2bfloat162_rn(f0.z, f0.w);
    p[2] = __floats2bfloat162_rn(f1.x, f1.y);
    p[3] = __floats2bfloat162_rn(f1.z, f1.w);
    *reinterpret_cast<uint4*>(g_Wb + base) = *reinterpret_cast<uint4*>(p);
}

// ===========================================================================
// GEMM: Y = tanh(H[1024,7168] @ Wb[12544,7168]^T + bias)    (both bf16)
// WMMA m16n16k16, CTA tile 128x256, warp tile 64x64 (8 warps, 2x4),
// BK=32, 6-stage cp.async pipeline, ONE __syncthreads per k-iteration.
// (byte-identical to the R13/R15 pass)
// ===========================================================================
#define NKT      224         // 7168 / 32
#define NSTG     6
#define AST      10240       // A stage bytes: 128 rows * 80B (stride 40 bf16)
#define STG      30720       // A + B per stage
#define ROWB     80          // bytes per smem row (40 bf16)

__global__ void __launch_bounds__(256, 1)
gemm_kernel(const float* __restrict__ bias, float* __restrict__ Y)
{
    extern __shared__ char smem_raw[];
    const uint32_t sbase = smem_u32(smem_raw);
    __nv_bfloat16* sA = reinterpret_cast<__nv_bfloat16*>(smem_raw);

    const int tid  = threadIdx.x;
    const int wid  = tid >> 5;
    const int lane = tid & 31;
    const int wm   = wid >> 2;           // 2 warp rows (M, 64 each)
    const int wn   = wid & 3;            // 4 warp cols (N, 64 each)
    const int am   = blockIdx.x * 128;   // M tile (x fastest -> W L2 reuse)
    const int bn   = blockIdx.y * 256;   // N tile

    const __nv_bfloat16* A = g_H;
    const __nv_bfloat16* B = g_Wb;

    wmma::fragment<wmma::accumulator, 16, 16, 16, float> acc[4][4];
    #pragma unroll
    for (int i = 0; i < 4; i++)
        #pragma unroll
        for (int j = 0; j < 4; j++)
            wmma::fill_fragment(acc[i][j], 0.f);

    // stage loader: 1536 x 16B chunks (512 A + 1024 B), 6 per thread
    auto load_stage = [&](int it) {
        const uint32_t ss = sbase + (it % NSTG) * STG;
        const int k0 = it * 32;
        #pragma unroll
        for (int u = 0; u < 2; u++) {              // A: ids 0..511
            int id  = tid + u * 256;
            int row = id >> 2, q = id & 3;
            cp_async16(ss + row * ROWB + q * 16,
                       A + (size_t)(am + row) * GK + k0 + q * 8);
        }
        #pragma unroll
        for (int u = 0; u < 4; u++) {              // B: ids 0..1023
            int id  = tid + u * 256;
            int row = id >> 2, q = id & 3;
            cp_async16(ss + AST + row * ROWB + q * 16,
                       B + (size_t)(bn + row) * GK + k0 + q * 8);
        }
    };

    // prologue: stages 0..4 (5 groups in flight)
    load_stage(0); CP_COMMIT();
    load_stage(1); CP_COMMIT();
    load_stage(2); CP_COMMIT();
    load_stage(3); CP_COMMIT();
    load_stage(4); CP_COMMIT();

    for (int kt = 0; kt < NKT; kt++) {
        CP_WAIT4();                  // stage kt resident (<=4 groups pending)
        __syncthreads();             // all threads see stage kt; all done with
                                     // slot (kt-1)%6 which we overwrite below

        const int s = kt % NSTG;
        const __nv_bfloat16* As = sA + s * (STG / 2);
        const __nv_bfloat16* Bs = As + (AST / 2);
        #pragma unroll
        for (int kk = 0; kk < 32; kk += 16) {
            wmma::fragment<wmma::matrix_a, 16, 16, 16, __nv_bfloat16, wmma::row_major> fa[4];
            wmma::fragment<wmma::matrix_b, 16, 16, 16, __nv_bfloat16, wmma::col_major> fb[4];
            #pragma unroll
            for (int i = 0; i < 4; i++)
                wmma::load_matrix_sync(fa[i], As + (wm * 64 + i * 16) * 40 + kk, 40);
            #pragma unroll
            for (int j = 0; j < 4; j++)
                wmma::load_matrix_sync(fb[j], Bs + (wn * 64 + j * 16) * 40 + kk, 40);
            #pragma unroll
            for (int i = 0; i < 4; i++)
                #pragma unroll
                for (int j = 0; j < 4; j++)
                    wmma::mma_sync(acc[i][j], fa[i], fb[j], acc[i][j]);
        }

        // prefetch stage kt+5 into slot (kt+5)%6 == (kt-1)%6 (safe: consumed
        // before the barrier above)
        if (kt + 5 < NKT) load_stage(kt + 5);
        CP_COMMIT();                 // one group per iteration (may be empty)
    }
    CP_WAIT0();
    __syncthreads();

    // --- epilogue: bias + tanh, per-warp smem scratch (stride 20 floats) ---
    float* scr = reinterpret_cast<float*>(smem_raw) + wid * (16 * 20);
    #pragma unroll
    for (int fm = 0; fm < 4; fm++) {
        #pragma unroll
        for (int fn = 0; fn < 4; fn++) {
            wmma::store_matrix_sync(scr, acc[fm][fn], 20, wmma::mem_row_major);
            __syncwarp();
            int gm0 = am + wm * 64 + fm * 16;
            int gn0 = bn + wn * 64 + fn * 16;
            #pragma unroll
            for (int e = lane; e < 256; e += 32) {
                int r = e >> 4, c = e & 15;
                int gn = gn0 + c;
                float v = tanhf(scr[r * 20 + c] + __ldg(bias + gn));
                Y[(size_t)(gm0 + r) * GN + gn] = v;
            }
            __syncwarp();
        }
    }
}

// ===========================================================================
// Epilogue: in-place symmetrize + arctanh + diagonal (smem-tiled).
// Transpose buffer stride 113 (odd): the strided read walks all 32 banks.
// ===========================================================================
__global__ void __launch_bounds__(256)
epi_kernel(float* __restrict__ out)
{
    extern __shared__ float sY[];          // 112*113 floats
    int b   = blockIdx.x;
    int tid = threadIdx.x;
    float* Yb = out + (size_t)b * GN;

    for (int i = tid; i < GN; i += 256) {
        int r = i / NN, c = i - r * NN;
        sY[r * EPIS + c] = Yb[i];
    }
    __syncthreads();

    for (int i = tid; i < GN; i += 256) {
        int r = i / NN;
        int c = i - r * NN;
        float v;
        if (r == c) v = 1.0f;
        else        v = atanhf(0.4995f * (sY[r * EPIS + c] + sY[c * EPIS + r]));
        Yb[i] = v;
    }
}

// ===========================================================================
// Launch
// ===========================================================================
extern "C" void kernel_launch(void* const* d_in, const int* in_sizes, int n_in,
                              void* d_out, int out_size)
{
    const float* x     = (const float*)d_in[0];
    const float* a     = (const float*)d_in[1];
    const int*   label = (const int*)  d_in[2];
    const float* We1   = (const float*)d_in[3];
    const float* be1   = (const float*)d_in[4];
    const float* We2   = (const float*)d_in[5];
    const float* be2   = (const float*)d_in[6];
    const float* Wg1   = (const float*)d_in[7];
    const float* bg1   = (const float*)d_in[8];
    const float* Wg2   = (const float*)d_in[9];
    const float* bg2   = (const float*)d_in[10];
    const float* Wlin  = (const float*)d_in[11];
    const float* blin  = (const float*)d_in[12];
    const float* emb   = (const float*)d_in[13];
    float* out = (float*)d_out;

    const int gnn_smem  = (12992 + 3 * 14784) * 4;   // 229376 B
    const int gemm_smem = NSTG * STG;                // 184320 B
    const int epi_smem  = NN * EPIS * 4;             // 50624 B
    cudaFuncSetAttribute(gnn_kernel,  cudaFuncAttributeMaxDynamicSharedMemorySize, gnn_smem);
    cudaFuncSetAttribute(gemm_kernel, cudaFuncAttributeMaxDynamicSharedMemorySize, gemm_smem);
    cudaFuncSetAttribute(epi_kernel,  cudaFuncAttributeMaxDynamicSharedMemorySize, epi_smem);

    gnn_kernel<<<BATCH, 512, gnn_smem>>>(x, a, label, We1, be1, We2, be2,
                                         Wg1, bg1, Wg2, bg2, emb);

    // W fp32 -> bf16: 89,915,392 elems / (8 * 256) per block, zero smem
    wconv_kernel<<<(int)(((size_t)GN * GK) / 2048), 256>>>(Wlin);

    dim3 ggrid(BATCH / 128, GN / 256);   // (8, 49)
    gemm_kernel<<<ggrid, 256, gemm_smem>>>(blin, out);

    epi_kernel<<<BATCH, 256, epi_smem>>>(out);
}